// round 8
// baseline (speedup 1.0000x reference)
#include <cuda_runtime.h>
#include <cstdint>

// LIF scan over time axis. x: [rows, T=100] fp32, T contiguous.
// mem = prev_sp ? x : (mem*DECAY + x);  sp = mem > THRESH  (rounding-identical
// to reference's mem*DECAY*(1-sp)+x since sp is exactly 0 or 1).
//
// R8: bulk-TMA in-place 4-deep ring + DYNAMIC WORK-STEALING (global atomic
// chunk counter). All 152 SMs participate when free; balance is automatic
// (+-1 chunk) and robust to dirty waves: late CTAs just steal fewer chunks,
// so no straggler round can form. Counter reset by a captured init kernel.

#define LIF_THRESH 0.5f
#define LIF_DECAY  0.2f
#define LIF_T      100
#define LIF_TV     25                          // float4 per row (odd stride -> conflict-free)
#define CHUNK_ROWS 128
#define THREADS    128
#define NBUF       4
#define CHUNK_BYTES (CHUNK_ROWS * LIF_T * 4)   // 51200
#define SM_ID       64                          // s_id[4] ints at byte 64
#define SM_IN       1024                        // buffers after mbars/ids
#define SM_TOTAL    (SM_IN + NBUF * CHUNK_BYTES)  // 205824 bytes -> 1 CTA/SM

__device__ unsigned int g_next_chunk;

__global__ void lif_reset_kernel() { g_next_chunk = 0u; }

__device__ __forceinline__ uint32_t smem_u32(const void* p) {
    uint32_t a;
    asm("{ .reg .u64 t; cvta.to.shared.u64 t, %1; cvt.u32.u64 %0, t; }" : "=r"(a) : "l"(p));
    return a;
}
__device__ __forceinline__ void mbar_init(uint32_t mbar, uint32_t cnt) {
    asm volatile("mbarrier.init.shared.b64 [%0], %1;" :: "r"(mbar), "r"(cnt) : "memory");
}
__device__ __forceinline__ void mbar_expect(uint32_t mbar, uint32_t bytes) {
    asm volatile("mbarrier.arrive.expect_tx.shared.b64 _, [%0], %1;" :: "r"(mbar), "r"(bytes) : "memory");
}
__device__ __forceinline__ void mbar_wait(uint32_t mbar, uint32_t parity) {
    uint32_t done;
    asm volatile(
        "{\n\t.reg .pred p;\n\t"
        "mbarrier.try_wait.parity.acquire.cta.shared::cta.b64 p, [%1], %2;\n\t"
        "selp.b32 %0, 1, 0, p;\n\t}"
        : "=r"(done) : "r"(mbar), "r"(parity) : "memory");
    if (!done) {
        asm volatile(
            "{\n\t.reg .pred P1;\n\t"
            "W_%=:\n\t"
            "mbarrier.try_wait.parity.acquire.cta.shared::cta.b64 P1, [%0], %1, 0x989680;\n\t"
            "@P1 bra.uni D_%=;\n\t"
            "bra.uni W_%=;\n\t"
            "D_%=:\n\t}"
            :: "r"(mbar), "r"(parity) : "memory");
    }
}
__device__ __forceinline__ void bulk_g2s(uint32_t dst_smem, const void* src, uint32_t bytes, uint32_t mbar) {
    asm volatile(
        "cp.async.bulk.shared::cluster.global.mbarrier::complete_tx::bytes [%0], [%1], %2, [%3];"
        :: "r"(dst_smem), "l"(src), "r"(bytes), "r"(mbar) : "memory");
}
__device__ __forceinline__ void bulk_s2g(void* dst, uint32_t src_smem, uint32_t bytes) {
    asm volatile(
        "cp.async.bulk.global.shared::cta.bulk_group [%0], [%1], %2;"
        :: "l"(dst), "r"(src_smem), "r"(bytes) : "memory");
}

__global__ __launch_bounds__(THREADS, 1)
void lif_tma_kernel(const char* __restrict__ gin, char* __restrict__ gout,
                    unsigned int n_chunks) {
    extern __shared__ char smem[];
    const uint32_t sbase = smem_u32(smem);
    const int tid = threadIdx.x;
    int* s_id = (int*)(smem + SM_ID);   // chunk id held by each ring slot (-1 = none)

    if (tid == 0) {
        #pragma unroll
        for (int b = 0; b < NBUF; b++) mbar_init(sbase + 8 * b, 1);
        asm volatile("fence.proxy.async.shared::cta;" ::: "memory");
        // Prologue: steal up to 3 chunks and start their loads.
        for (int l = 0; l < 3; l++) {
            unsigned int id = atomicAdd(&g_next_chunk, 1u);
            int v = (id < n_chunks) ? (int)id : -1;
            s_id[l] = v;
            if (v >= 0) {
                mbar_expect(sbase + 8 * l, CHUNK_BYTES);
                bulk_g2s(sbase + SM_IN + l * CHUNK_BYTES,
                         gin + (long long)v * CHUNK_BYTES, CHUNK_BYTES, sbase + 8 * l);
            }
        }
    }
    __syncthreads();

    unsigned int ph = 0;   // per-buffer parity bits (all threads in lockstep)

    for (int l = 0; ; l++) {
        const int b = l & (NBUF - 1);
        const int gid = s_id[b];         // written >=1 barrier ago
        if (gid < 0) break;              // uniform across the CTA

        // Refill the pipeline BEFORE scanning: slot (l+3)&3 held chunk of
        // iter l-1, whose store was committed at the end of iter l-1;
        // wait_group.read 0 guarantees its smem has been fully read out.
        if (tid == 0) {
            asm volatile("cp.async.bulk.wait_group.read 0;" ::: "memory");
            const int nb = (l + 3) & (NBUF - 1);
            unsigned int id = atomicAdd(&g_next_chunk, 1u);
            int v = (id < n_chunks) ? (int)id : -1;
            s_id[nb] = v;
            if (v >= 0) {
                mbar_expect(sbase + 8 * nb, CHUNK_BYTES);
                bulk_g2s(sbase + SM_IN + nb * CHUNK_BYTES,
                         gin + (long long)v * CHUNK_BYTES, CHUNK_BYTES, sbase + 8 * nb);
            }
        }

        // Wait for this slot's load.
        mbar_wait(sbase + 8 * b, (ph >> b) & 1u);
        ph ^= (1u << b);

        // Streaming in-place scan: read f4, compute, write spikes back.
        float4* row = (float4*)(smem + SM_IN + b * CHUNK_BYTES) + tid * LIF_TV;
        float mem = 0.0f;
        bool sp = false;
        #pragma unroll
        for (int k = 0; k < LIF_TV; k++) {
            float4 v = row[k];
            float4 o;
            float t;
            t = __fadd_rn(__fmul_rn(mem, LIF_DECAY), v.x);
            mem = sp ? v.x : t;  sp = mem > LIF_THRESH;  o.x = sp ? 1.0f : 0.0f;
            t = __fadd_rn(__fmul_rn(mem, LIF_DECAY), v.y);
            mem = sp ? v.y : t;  sp = mem > LIF_THRESH;  o.y = sp ? 1.0f : 0.0f;
            t = __fadd_rn(__fmul_rn(mem, LIF_DECAY), v.z);
            mem = sp ? v.z : t;  sp = mem > LIF_THRESH;  o.z = sp ? 1.0f : 0.0f;
            t = __fadd_rn(__fmul_rn(mem, LIF_DECAY), v.w);
            mem = sp ? v.w : t;  sp = mem > LIF_THRESH;  o.w = sp ? 1.0f : 0.0f;
            row[k] = o;
        }

        // Publish STS to the async proxy, then store this chunk.
        asm volatile("fence.proxy.async.shared::cta;" ::: "memory");
        __syncthreads();
        if (tid == 0) {
            bulk_s2g(gout + (long long)gid * CHUNK_BYTES,
                     sbase + SM_IN + b * CHUNK_BYTES, CHUNK_BYTES);
            asm volatile("cp.async.bulk.commit_group;" ::: "memory");
        }
    }

    // Keep smem alive until all pending bulk stores have read it.
    if (tid == 0)
        asm volatile("cp.async.bulk.wait_group.read 0;" ::: "memory");
}

// Scalar tail for rows not covered by full chunks.
__global__ void lif_scan_tail_kernel(const float* __restrict__ x,
                                     float* __restrict__ out,
                                     long long row_start, long long n_rows) {
    long long r = row_start + blockIdx.x * (long long)blockDim.x + threadIdx.x;
    if (r >= n_rows) return;
    const float* xr = x + r * LIF_T;
    float* orow = out + r * LIF_T;
    float mem = 0.0f;
    bool sp = false;
    #pragma unroll 4
    for (int t = 0; t < LIF_T; t++) {
        float tt = __fadd_rn(__fmul_rn(mem, LIF_DECAY), xr[t]);
        mem = sp ? xr[t] : tt;
        sp = mem > LIF_THRESH;
        orow[t] = sp ? 1.0f : 0.0f;
    }
}

extern "C" void kernel_launch(void* const* d_in, const int* in_sizes, int n_in,
                              void* d_out, int out_size) {
    const float* x = (const float*)d_in[0];
    float* out = (float*)d_out;

    long long total = (long long)in_sizes[0];
    long long n_rows = total / LIF_T;                 // 524288
    long long n_chunks = n_rows / CHUNK_ROWS;         // 4096

    if (n_chunks > 0) {
        cudaFuncSetAttribute(lif_tma_kernel,
                             cudaFuncAttributeMaxDynamicSharedMemorySize, SM_TOTAL);
        // Reset the work-stealing counter (captured into the graph, so every
        // replay re-runs it -> deterministic).
        lif_reset_kernel<<<1, 1>>>();
        // All 152 SMs; dynamic stealing keeps balance even if the wave is
        // dirty (late CTAs just steal fewer chunks).
        long long grid = 152;
        if (n_chunks < grid) grid = n_chunks;
        lif_tma_kernel<<<(unsigned)grid, THREADS, SM_TOTAL>>>(
            (const char*)x, (char*)out, (unsigned int)n_chunks);
    }

    long long done_rows = n_chunks * CHUNK_ROWS;
    long long rem = n_rows - done_rows;
    if (rem > 0) {
        int threads = 128;
        int blocks = (int)((rem + threads - 1) / threads);
        lif_scan_tail_kernel<<<blocks, threads>>>(x, out, done_rows, n_rows);
    }
}